// round 7
// baseline (speedup 1.0000x reference)
#include <cuda_runtime.h>
#include <cuda_bf16.h>

#define BATCH 256
#define PPAIR 1024
#define TPTS  100
#define NGRID 65536
#define NB    (TPTS + 1)   // mid-buckets 0..100
#define NBINS (2 * NB)
#define SENT  (-1e30f)

__device__ __forceinline__ void top2_upd(float v, float& a1, float& a2) {
    a2 = fmaxf(a2, fminf(a1, v));
    a1 = fmaxf(a1, v);
}
__device__ __forceinline__ float2 top2_merge(float2 a, float2 b) {
    float lo = fminf(a.x, b.x);
    return make_float2(fmaxf(a.x, b.x), fmaxf(lo, fmaxf(a.y, b.y)));
}

__global__ __launch_bounds__(1024, 2)
void pl_kernel(const float* __restrict__ inputs,
               const int*   __restrict__ dim_idx,
               const int*   __restrict__ birth_loc,
               const int*   __restrict__ death_loc,
               float* __restrict__ land,    // [B, 2, T, 2]
               float* __restrict__ trange)  // [B, 4]
{
    __shared__ float  s_b[PPAIR], s_d[PPAIR];
    __shared__ unsigned s_mask[32];                 // per-warp dim==1 ballots
    __shared__ __align__(16) float2 s_pr[PPAIR];    // scattered (d, -b)
    __shared__ int    s_hist[NBINS];                // histogram -> scatter cursor
    __shared__ int    s_off[NBINS + 1];
    __shared__ __align__(16) float2 s_scan[4][128]; // [dim*2+side][bucket] top2
    __shared__ int    s_wtot[7];
    __shared__ int    s_cnt[2];
    __shared__ float  s_tmin[2], s_tmax[2];
    __shared__ unsigned s_max[2];

    const int b    = blockIdx.x;
    const int tid  = threadIdx.x;
    const int lane = tid & 31;
    const int w    = tid >> 5;

    if (tid < NBINS) s_hist[tid] = 0;
    if (tid < 2) s_max[tid] = 0u;

    const float* __restrict__ row = inputs + (size_t)b * NGRID;

    // ---- A: gather one pair per thread (hist zeroing overlaps these loads)
    const int   dm = dim_idx  [b * PPAIR + tid];
    const float vb = __ldg(row + birth_loc[b * PPAIR + tid]);
    const float vd = __ldg(row + death_loc[b * PPAIR + tid]);
    s_b[tid] = vb; s_d[tid] = vd;
    {
        unsigned mk1 = __ballot_sync(0xffffffffu, dm == 1);
        if (lane == 0) s_mask[w] = mk1;
    }
    const float mid = 0.5f * (vb + vd);
    __syncthreads();                                            // (1)

    // ---- B: t-range from FIRST 2 valid pairs (bit-scan of 32 ballot words)
    if (tid < 2) {
        const int dim = tid;
        float tmin = 1e30f, tmax = -1e30f;
        int found = 0, cnt = 0;
        #pragma unroll 4
        for (int ww = 0; ww < 32; ww++) {
            unsigned m = s_mask[ww];
            if (dim == 0) m = ~m;
            cnt += __popc(m);
            while (m && found < 2) {
                int l = __ffs(m) - 1; m &= m - 1;
                int p = ww * 32 + l;
                tmin = fminf(tmin, s_b[p]);
                tmax = fmaxf(tmax, s_d[p]);
                found++;
            }
        }
        if (cnt == 0) { tmin = 0.0f; tmax = 0.0f; }
        s_cnt[dim] = cnt; s_tmin[dim] = tmin; s_tmax[dim] = tmax;
    }
    __syncthreads();                                            // (2)

    // ---- C: bucket c = smallest j with tv_j >= mid; histogram
    int bin;
    {
        const float tmn  = s_tmin[dm], tmx = s_tmax[dm];
        const float num  = mid - tmn;
        const float step = (tmx - tmn) * (1.0f / (float)(TPTS - 1));
        int c;
        if (num <= 0.0f)       c = 0;
        else if (step <= 0.0f) c = NB - 1;
        else                   c = min(NB - 1, (int)ceilf(num / step));
        bin = dm * NB + c;
        atomicAdd(&s_hist[bin], 1);
    }
    __syncthreads();                                            // (3)

    // ---- D: exclusive prefix over 202 bins (7 warps, shfl scan)
    if (tid < 224) {
        int v = (tid < NBINS) ? s_hist[tid] : 0;
        int iv = v;
        #pragma unroll
        for (int o = 1; o < 32; o <<= 1) {
            int n = __shfl_up_sync(0xffffffffu, iv, o);
            if (lane >= o) iv += n;
        }
        if (lane == 31) s_wtot[w] = iv;
        s_off[tid] = iv - v;                 // warp-local exclusive (temp)
    }
    __syncthreads();                                            // (4)
    if (tid < NBINS) {
        int base = 0;
        #pragma unroll
        for (int q = 0; q < 7; q++) if (q < w) base += s_wtot[q];
        int excl = s_off[tid] + base;
        s_off[tid] = excl;
        s_hist[tid] = excl;                  // scatter cursor
    }
    if (tid == 0) s_off[NBINS] = PPAIR;
    __syncthreads();                                            // (5)

    // ---- E: scatter (d, -b) bucket-contiguously
    {
        int pos = atomicAdd(&s_hist[bin], 1);
        s_pr[pos] = make_float2(vd, -vb);
    }
    __syncthreads();                                            // (6)

    // ---- F: per-bin top2 of d and of -b
    if (tid < NBINS) {
        const int dim = (tid >= NB), c = tid - dim * NB;
        const int st = s_off[tid], en = s_off[tid + 1];
        float d1 = SENT, d2 = SENT, n1 = SENT, n2 = SENT;
        for (int i = st; i < en; i++) {
            float2 e = s_pr[i];
            top2_upd(e.x, d1, d2);
            top2_upd(e.y, n1, n2);
        }
        s_scan[dim * 2 + 0][c] = make_float2(d1, d2);
        s_scan[dim * 2 + 1][c] = make_float2(n1, n2);
    }
    __syncthreads();                                            // (7)

    // ---- G: 4 warps, in-register top2 scan (side0 prefix asc, side1 suffix desc)
    if (w < 4) {
        const int side = w & 1;
        float2 r[4];
        float2 acc = make_float2(SENT, SENT);
        #pragma unroll
        for (int k = 0; k < 4; k++) {
            int idx = lane * 4 + k;
            int j   = side ? 127 - idx : idx;
            float2 e = (j <= NB - 1) ? s_scan[w][j] : make_float2(SENT, SENT);
            acc = top2_merge(acc, e);
            r[k] = acc;
        }
        float2 sc = acc;
        #pragma unroll
        for (int o = 1; o < 32; o <<= 1) {
            float2 ox;
            ox.x = __shfl_up_sync(0xffffffffu, sc.x, o);
            ox.y = __shfl_up_sync(0xffffffffu, sc.y, o);
            if (lane >= o) sc = top2_merge(sc, ox);
        }
        float2 ex;
        ex.x = __shfl_up_sync(0xffffffffu, sc.x, 1);
        ex.y = __shfl_up_sync(0xffffffffu, sc.y, 1);
        if (lane == 0) ex = make_float2(SENT, SENT);
        #pragma unroll
        for (int k = 0; k < 4; k++) {
            int idx = lane * 4 + k;
            int j   = side ? 127 - idx : idx;
            s_scan[w][j] = top2_merge(ex, r[k]);    // in-place: own entries only
        }
    }
    __syncthreads();                                            // (8)

    // ---- H: finalize per (dim, t)
    if (tid < 256) {
        const int dim = tid >> 7;
        const int t   = tid & 127;
        float m1 = 0.0f;
        if (t < TPTS) {
            const float tmn = s_tmin[dim], tmx = s_tmax[dim];
            const float tv  = tmn + (tmx - tmn) * ((float)t * (1.0f / (float)(TPTS - 1)));
            float2 A  = s_scan[dim * 2 + 0][t];      // mids in buckets 0..t
            float2 Bs = s_scan[dim * 2 + 1][t + 1];  // mids in buckets t+1..
            float vA1 = A.x - tv,  vA2 = A.y - tv;   // d - tv
            float vB1 = Bs.x + tv, vB2 = Bs.y + tv;  // tv - b
            m1 = fmaxf(0.0f, fmaxf(vA1, vB1));
            float s2 = fmaxf(fminf(vA1, vB1), (vA1 >= vB1) ? vA2 : vB2);
            float m2 = fmaxf(0.0f, s2);
            *(float2*)&land[((size_t)(b * 2 + dim) * TPTS + t) * 2] =
                make_float2(m1, m2);
        }
        unsigned wm = __reduce_max_sync(0xffffffffu, __float_as_uint(m1));
        if (lane == 0) atomicMax(&s_max[dim], wm);  // m1 >= 0: bit order OK
    }
    __syncthreads();                                            // (9)

    if (tid < 2) {
        bool nz = (s_cnt[tid] > 0) && (__uint_as_float(s_max[tid]) > 0.0f);
        trange[b * 4 + 2 * tid + 0] = nz ? s_tmin[tid] : 0.0f;
        trange[b * 4 + 2 * tid + 1] = nz ? s_tmax[tid] : 0.0f;
    }
}

extern "C" void kernel_launch(void* const* d_in, const int* in_sizes, int n_in,
                              void* d_out, int out_size) {
    const float* inputs    = (const float*)d_in[0];
    const int*   dim_idx   = (const int*)  d_in[1];
    const int*   birth_loc = (const int*)  d_in[2];
    const int*   death_loc = (const int*)  d_in[3];

    float* land   = (float*)d_out;                        // B*2*T*2 = 102400
    float* trange = land + (size_t)BATCH * 2 * TPTS * 2;  // B*4     = 1024

    pl_kernel<<<BATCH, 1024>>>(inputs, dim_idx, birth_loc, death_loc, land, trange);
}

// round 9
// speedup vs baseline: 1.0210x; 1.0210x over previous
#include <cuda_runtime.h>
#include <cuda_bf16.h>

#define BATCH 256
#define PPAIR 1024
#define TPTS  100
#define NGRID 65536
#define NB    (TPTS + 1)   // mid-buckets 0..100
#define NBINS (2 * NB)
#define SENT  (-1e30f)

__device__ __forceinline__ void top2_upd(float v, float& a1, float& a2) {
    a2 = fmaxf(a2, fminf(a1, v));
    a1 = fmaxf(a1, v);
}
__device__ __forceinline__ float2 top2_merge(float2 a, float2 b) {
    float lo = fminf(a.x, b.x);
    return make_float2(fmaxf(a.x, b.x), fmaxf(lo, fmaxf(a.y, b.y)));
}

__global__ __launch_bounds__(1024, 2)
void pl_kernel(const float* __restrict__ inputs,
               const int*   __restrict__ dim_idx,
               const int*   __restrict__ birth_loc,
               const int*   __restrict__ death_loc,
               float* __restrict__ land,    // [B, 2, T, 2]
               float* __restrict__ trange)  // [B, 4]
{
    __shared__ float  s_b[PPAIR], s_d[PPAIR];
    __shared__ unsigned s_mask[32];                 // per-warp dim==1 ballots
    __shared__ __align__(16) float2 s_pr[PPAIR];    // scattered (d, -b)
    __shared__ int    s_hist[NBINS];                // histogram -> scatter cursor
    __shared__ int    s_off[NBINS + 1];
    __shared__ __align__(16) float2 s_scan[4][128]; // [dim*2+side][bucket] top2
    __shared__ int    s_wtot[7];
    __shared__ int    s_cnt[2];
    __shared__ float  s_tmin[2], s_tmax[2];
    __shared__ unsigned s_max[2];

    const int b    = blockIdx.x;
    const int tid  = threadIdx.x;
    const int lane = tid & 31;
    const int w    = tid >> 5;

    // ---- A: issue all loads ASAP (indices streaming; gathers L2-only)
    const int   dm = __ldcs(dim_idx   + b * PPAIR + tid);
    const int   bl = __ldcs(birth_loc + b * PPAIR + tid);
    const int   dl = __ldcs(death_loc + b * PPAIR + tid);
    const float* __restrict__ row = inputs + (size_t)b * NGRID;
    const float vb = __ldcg(row + bl);
    const float vd = __ldcg(row + dl);

    if (tid < NBINS) s_hist[tid] = 0;
    if (tid < 2) s_max[tid] = 0u;

    s_b[tid] = vb; s_d[tid] = vd;
    {
        unsigned mk1 = __ballot_sync(0xffffffffu, dm == 1);
        if (lane == 0) s_mask[w] = mk1;
    }
    const float mid = 0.5f * (vb + vd);
    __syncthreads();                                            // (1)

    // ---- B: t-range from FIRST 2 valid pairs (bit-scan of 32 ballot words)
    if (tid < 2) {
        const int dim = tid;
        float tmin = 1e30f, tmax = -1e30f;
        int found = 0, cnt = 0;
        #pragma unroll 4
        for (int ww = 0; ww < 32; ww++) {
            unsigned m = s_mask[ww];
            if (dim == 0) m = ~m;
            cnt += __popc(m);
            while (m && found < 2) {
                int l = __ffs(m) - 1; m &= m - 1;
                int p = ww * 32 + l;
                tmin = fminf(tmin, s_b[p]);
                tmax = fmaxf(tmax, s_d[p]);
                found++;
            }
        }
        if (cnt == 0) { tmin = 0.0f; tmax = 0.0f; }
        s_cnt[dim] = cnt; s_tmin[dim] = tmin; s_tmax[dim] = tmax;
    }
    __syncthreads();                                            // (2)

    // ---- C: bucket c = smallest j with tv_j >= mid; histogram
    int bin;
    {
        const float tmn  = s_tmin[dm], tmx = s_tmax[dm];
        const float num  = mid - tmn;
        const float step = (tmx - tmn) * (1.0f / (float)(TPTS - 1));
        int c;
        if (num <= 0.0f)       c = 0;
        else if (step <= 0.0f) c = NB - 1;
        else                   c = min(NB - 1, (int)ceilf(num / step));
        bin = dm * NB + c;
        atomicAdd(&s_hist[bin], 1);
    }
    __syncthreads();                                            // (3)

    // ---- D: exclusive prefix over 202 bins (7 warps, shfl scan)
    if (tid < 224) {
        int v = (tid < NBINS) ? s_hist[tid] : 0;
        int iv = v;
        #pragma unroll
        for (int o = 1; o < 32; o <<= 1) {
            int n = __shfl_up_sync(0xffffffffu, iv, o);
            if (lane >= o) iv += n;
        }
        if (lane == 31) s_wtot[w] = iv;
        s_off[tid] = iv - v;                 // warp-local exclusive (temp)
    }
    __syncthreads();                                            // (4)
    if (tid < NBINS) {
        int base = 0;
        #pragma unroll
        for (int q = 0; q < 7; q++) if (q < w) base += s_wtot[q];
        int excl = s_off[tid] + base;
        s_off[tid] = excl;
        s_hist[tid] = excl;                  // scatter cursor
    }
    if (tid == 0) s_off[NBINS] = PPAIR;
    __syncthreads();                                            // (5)

    // ---- E: scatter (d, -b) bucket-contiguously
    {
        int pos = atomicAdd(&s_hist[bin], 1);
        s_pr[pos] = make_float2(vd, -vb);
    }
    __syncthreads();                                            // (6)

    // ---- F: per-bin top2 of d and of -b
    if (tid < NBINS) {
        const int dim = (tid >= NB), c = tid - dim * NB;
        const int st = s_off[tid], en = s_off[tid + 1];
        float d1 = SENT, d2 = SENT, n1 = SENT, n2 = SENT;
        for (int i = st; i < en; i++) {
            float2 e = s_pr[i];
            top2_upd(e.x, d1, d2);
            top2_upd(e.y, n1, n2);
        }
        s_scan[dim * 2 + 0][c] = make_float2(d1, d2);
        s_scan[dim * 2 + 1][c] = make_float2(n1, n2);
    }
    __syncthreads();                                            // (7)

    // ---- G: 4 warps, in-register top2 scan (side0 prefix asc, side1 suffix desc)
    if (w < 4) {
        const int side = w & 1;
        float2 r[4];
        float2 acc = make_float2(SENT, SENT);
        #pragma unroll
        for (int k = 0; k < 4; k++) {
            int idx = lane * 4 + k;
            int j   = side ? 127 - idx : idx;
            float2 e = (j <= NB - 1) ? s_scan[w][j] : make_float2(SENT, SENT);
            acc = top2_merge(acc, e);
            r[k] = acc;
        }
        float2 sc = acc;
        #pragma unroll
        for (int o = 1; o < 32; o <<= 1) {
            float2 ox;
            ox.x = __shfl_up_sync(0xffffffffu, sc.x, o);
            ox.y = __shfl_up_sync(0xffffffffu, sc.y, o);
            if (lane >= o) sc = top2_merge(sc, ox);
        }
        float2 ex;
        ex.x = __shfl_up_sync(0xffffffffu, sc.x, 1);
        ex.y = __shfl_up_sync(0xffffffffu, sc.y, 1);
        if (lane == 0) ex = make_float2(SENT, SENT);
        #pragma unroll
        for (int k = 0; k < 4; k++) {
            int idx = lane * 4 + k;
            int j   = side ? 127 - idx : idx;
            s_scan[w][j] = top2_merge(ex, r[k]);    // in-place: own entries only
        }
    }
    __syncthreads();                                            // (8)

    // ---- H: finalize per (dim, t)
    if (tid < 256) {
        const int dim = tid >> 7;
        const int t   = tid & 127;
        float m1 = 0.0f;
        if (t < TPTS) {
            const float tmn = s_tmin[dim], tmx = s_tmax[dim];
            const float tv  = tmn + (tmx - tmn) * ((float)t * (1.0f / (float)(TPTS - 1)));
            float2 A  = s_scan[dim * 2 + 0][t];      // mids in buckets 0..t
            float2 Bs = s_scan[dim * 2 + 1][t + 1];  // mids in buckets t+1..
            float vA1 = A.x - tv,  vA2 = A.y - tv;   // d - tv
            float vB1 = Bs.x + tv, vB2 = Bs.y + tv;  // tv - b
            m1 = fmaxf(0.0f, fmaxf(vA1, vB1));
            float s2 = fmaxf(fminf(vA1, vB1), (vA1 >= vB1) ? vA2 : vB2);
            float m2 = fmaxf(0.0f, s2);
            *(float2*)&land[((size_t)(b * 2 + dim) * TPTS + t) * 2] =
                make_float2(m1, m2);
        }
        unsigned wm = __reduce_max_sync(0xffffffffu, __float_as_uint(m1));
        if (lane == 0) atomicMax(&s_max[dim], wm);  // m1 >= 0: bit order OK
    }
    __syncthreads();                                            // (9)

    if (tid < 2) {
        bool nz = (s_cnt[tid] > 0) && (__uint_as_float(s_max[tid]) > 0.0f);
        trange[b * 4 + 2 * tid + 0] = nz ? s_tmin[tid] : 0.0f;
        trange[b * 4 + 2 * tid + 1] = nz ? s_tmax[tid] : 0.0f;
    }
}

extern "C" void kernel_launch(void* const* d_in, const int* in_sizes, int n_in,
                              void* d_out, int out_size) {
    const float* inputs    = (const float*)d_in[0];
    const int*   dim_idx   = (const int*)  d_in[1];
    const int*   birth_loc = (const int*)  d_in[2];
    const int*   death_loc = (const int*)  d_in[3];

    float* land   = (float*)d_out;                        // B*2*T*2 = 102400
    float* trange = land + (size_t)BATCH * 2 * TPTS * 2;  // B*4     = 1024

    pl_kernel<<<BATCH, 1024>>>(inputs, dim_idx, birth_loc, death_loc, land, trange);
}